// round 6
// baseline (speedup 1.0000x reference)
#include <cuda_runtime.h>
#include <cuda_bf16.h>

#define N 8192
#define MARGIN 0.2f
#define INV_LAMB 83.333336f   // 1 / 0.012

#define BLOCKS 256
#define ROWS_PER_BLOCK 32     // 256 * 32 = 8192
#define THREADS 512
#define CPT 16                // columns per thread: 512 * 16 = 8192
#define NU4 1024              // uint4 (8 bf16) per row
#define NF4 2048              // float4 per row
#define RGROUPS 16            // 256 partial rows -> 16 groups of 16
#define RB 8                  // rows per batch (fused / loss)
#define RB1 4                 // rows per batch (pass1, fp32 input)

// ---- scratch (static __device__ globals; no allocations) ----
__device__ uint4  g_K4[(size_t)N * N / 8];        // K in bf16 (128 MB)
__device__ float  g_r[N];
__device__ float  g_c[N];
__device__ float  g_d[N];
__device__ float  g_partial[(size_t)BLOCKS * N];  // col partials (8 MB)
__device__ float  g_partial2[(size_t)RGROUPS * N];// stage-2 partials (512 KB)
__device__ float  g_block_loss[BLOCKS];

__device__ __forceinline__ float warp_sum(float v) {
    v += __shfl_xor_sync(0xffffffffu, v, 16);
    v += __shfl_xor_sync(0xffffffffu, v, 8);
    v += __shfl_xor_sync(0xffffffffu, v, 4);
    v += __shfl_xor_sync(0xffffffffu, v, 2);
    v += __shfl_xor_sync(0xffffffffu, v, 1);
    return v;
}

__device__ __forceinline__ float2 unpack_bf2(unsigned u) {
    float2 f;
    f.x = __uint_as_float(u << 16);
    f.y = __uint_as_float(u & 0xffff0000u);
    return f;
}

__device__ __forceinline__ unsigned pack_bf2(float lo, float hi) {
    __nv_bfloat162 h = __floats2bfloat162_rn(lo, hi);
    return *reinterpret_cast<unsigned*>(&h);
}

__device__ __forceinline__ void unpack16(const uint4& a, const uint4& b, float* k) {
    float2 p;
    p = unpack_bf2(a.x); k[0] = p.x;  k[1] = p.y;
    p = unpack_bf2(a.y); k[2] = p.x;  k[3] = p.y;
    p = unpack_bf2(a.z); k[4] = p.x;  k[5] = p.y;
    p = unpack_bf2(a.w); k[6] = p.x;  k[7] = p.y;
    p = unpack_bf2(b.x); k[8] = p.x;  k[9] = p.y;
    p = unpack_bf2(b.y); k[10] = p.x; k[11] = p.y;
    p = unpack_bf2(b.z); k[12] = p.x; k[13] = p.y;
    p = unpack_bf2(b.w); k[14] = p.x; k[15] = p.y;
}

// ============================================================================
// pass1_fused: K = exp((s-1)/lamb) -> bf16 cache; row update with c == 1;
// col partials with new r.  Batched: RB1 rows per barrier, all loads up front.
// ============================================================================
__global__ __launch_bounds__(THREADS, 1) void pass1_fused(const float* __restrict__ sims) {
    int t = threadIdx.x;
    int wid = t >> 5, lane = t & 31;
    int row0 = blockIdx.x * ROWS_PER_BLOCK;
    __shared__ float red[2][RB1][16];

    const float4* __restrict__ sbase = (const float4*)sims + (size_t)row0 * NF4 + t * 4;
    uint4* __restrict__ kbase = g_K4 + (size_t)row0 * NU4 + t * 2;

    float acc[CPT];
    #pragma unroll
    for (int i = 0; i < CPT; i++) acc[i] = 0.f;

    for (int b = 0; b < ROWS_PER_BLOCK / RB1; b++) {
        int par = b & 1;
        // ---- issue ALL loads for the batch (MLP = 16) ----
        float4 sv[RB1][4];
        #pragma unroll
        for (int r = 0; r < RB1; r++) {
            const float4* p = sbase + (size_t)(b * RB1 + r) * NF4;
            #pragma unroll
            for (int q = 0; q < 4; q++) sv[r][q] = p[q];
        }
        // ---- exp, pack, store K, per-row partial sums ----
        uint4 kp[RB1][2];
        #pragma unroll
        for (int r = 0; r < RB1; r++) {
            float k[CPT];
            #pragma unroll
            for (int q = 0; q < 4; q++) {
                float4 s = sv[r][q];
                k[q * 4 + 0] = __expf((s.x - 1.0f) * INV_LAMB);
                k[q * 4 + 1] = __expf((s.y - 1.0f) * INV_LAMB);
                k[q * 4 + 2] = __expf((s.z - 1.0f) * INV_LAMB);
                k[q * 4 + 3] = __expf((s.w - 1.0f) * INV_LAMB);
            }
            kp[r][0].x = pack_bf2(k[0], k[1]);   kp[r][0].y = pack_bf2(k[2], k[3]);
            kp[r][0].z = pack_bf2(k[4], k[5]);   kp[r][0].w = pack_bf2(k[6], k[7]);
            kp[r][1].x = pack_bf2(k[8], k[9]);   kp[r][1].y = pack_bf2(k[10], k[11]);
            kp[r][1].z = pack_bf2(k[12], k[13]); kp[r][1].w = pack_bf2(k[14], k[15]);
            uint4* op = kbase + (size_t)(b * RB1 + r) * NU4;
            op[0] = kp[r][0]; op[1] = kp[r][1];

            float s0 = 0.f, s1 = 0.f, s2 = 0.f, s3 = 0.f;
            #pragma unroll
            for (int i = 0; i < CPT; i += 4) {
                s0 += k[i]; s1 += k[i + 1]; s2 += k[i + 2]; s3 += k[i + 3];
            }
            float s = warp_sum((s0 + s1) + (s2 + s3));
            if (lane == 0) red[par][r][wid] = s;
        }
        __syncthreads();
        // ---- finish row sums, accumulate col partials ----
        #pragma unroll
        for (int r = 0; r < RB1; r++) {
            float tot = 0.f;
            #pragma unroll
            for (int w = 0; w < 16; w++) tot += red[par][r][w];
            float ri = 1.0f / tot;
            if (t == r) g_r[row0 + b * RB1 + r] = ri;
            float k[CPT];
            unpack16(kp[r][0], kp[r][1], k);
            #pragma unroll
            for (int i = 0; i < CPT; i++) acc[i] += k[i] * ri;
        }
    }

    float4* out = (float4*)(g_partial + (size_t)blockIdx.x * N) + t * 4;
    #pragma unroll
    for (int q = 0; q < 4; q++)
        out[q] = make_float4(acc[q * 4], acc[q * 4 + 1], acc[q * 4 + 2], acc[q * 4 + 3]);
}

// ============================================================================
// fused_pass: r_i = 1/sum_j K_ij c_j, then col partials sum_i K_ij r_i.
// Batched: RB rows per barrier; 16 LDG.128 in flight per thread per batch.
// ============================================================================
__global__ __launch_bounds__(THREADS, 1) void fused_pass(void) {
    int t = threadIdx.x;
    int wid = t >> 5, lane = t & 31;
    int row0 = blockIdx.x * ROWS_PER_BLOCK;
    __shared__ float red[2][RB][16];

    const uint4* __restrict__ kbase = g_K4 + (size_t)row0 * NU4 + t * 2;

    float c[CPT];
    {
        const float4* cp = (const float4*)g_c + t * 4;
        #pragma unroll
        for (int q = 0; q < 4; q++) {
            float4 v = cp[q];
            c[q * 4] = v.x; c[q * 4 + 1] = v.y; c[q * 4 + 2] = v.z; c[q * 4 + 3] = v.w;
        }
    }
    float acc[CPT];
    #pragma unroll
    for (int i = 0; i < CPT; i++) acc[i] = 0.f;

    for (int b = 0; b < ROWS_PER_BLOCK / RB; b++) {
        int par = b & 1;
        // ---- issue ALL loads for the batch ----
        uint4 kp[RB][2];
        #pragma unroll
        for (int r = 0; r < RB; r++) {
            const uint4* p = kbase + (size_t)(b * RB + r) * NU4;
            kp[r][0] = p[0]; kp[r][1] = p[1];
        }
        // ---- per-row dot with c ----
        #pragma unroll
        for (int r = 0; r < RB; r++) {
            float k[CPT];
            unpack16(kp[r][0], kp[r][1], k);
            float s0 = 0.f, s1 = 0.f, s2 = 0.f, s3 = 0.f;
            #pragma unroll
            for (int i = 0; i < CPT; i += 4) {
                s0 += k[i] * c[i];
                s1 += k[i + 1] * c[i + 1];
                s2 += k[i + 2] * c[i + 2];
                s3 += k[i + 3] * c[i + 3];
            }
            float s = warp_sum((s0 + s1) + (s2 + s3));
            if (lane == 0) red[par][r][wid] = s;
        }
        __syncthreads();
        // ---- finish row sums, accumulate ----
        #pragma unroll
        for (int r = 0; r < RB; r++) {
            float tot = 0.f;
            #pragma unroll
            for (int w = 0; w < 16; w++) tot += red[par][r][w];
            float ri = 1.0f / tot;
            if (t == r) g_r[row0 + b * RB + r] = ri;
            float k[CPT];
            unpack16(kp[r][0], kp[r][1], k);
            #pragma unroll
            for (int i = 0; i < CPT; i++) acc[i] += k[i] * ri;
        }
    }

    float4* out = (float4*)(g_partial + (size_t)blockIdx.x * N) + t * 4;
    #pragma unroll
    for (int q = 0; q < 4; q++)
        out[q] = make_float4(acc[q * 4], acc[q * 4 + 1], acc[q * 4 + 2], acc[q * 4 + 3]);
}

// ============================================================================
// Two-stage tree reduction of g_partial[256][N] -> g_c
// ============================================================================
__global__ void col_reduce1(void) {
    int jv = blockIdx.x * 256 + threadIdx.x;   // float4 col index 0..2047
    int g  = blockIdx.y;
    const float4* __restrict__ p4 = (const float4*)g_partial;
    float4 acc = make_float4(0.f, 0.f, 0.f, 0.f);
    #pragma unroll
    for (int b = 0; b < 16; b++) {
        float4 p = p4[(size_t)(g * 16 + b) * (N / 4) + jv];
        acc.x += p.x; acc.y += p.y; acc.z += p.z; acc.w += p.w;
    }
    ((float4*)g_partial2)[(size_t)g * (N / 4) + jv] = acc;
}

__global__ void col_reduce2(void) {
    int jv = blockIdx.x * 256 + threadIdx.x;
    const float4* __restrict__ p4 = (const float4*)g_partial2;
    float4 acc = make_float4(0.f, 0.f, 0.f, 0.f);
    #pragma unroll
    for (int g = 0; g < RGROUPS; g++) {
        float4 p = p4[(size_t)g * (N / 4) + jv];
        acc.x += p.x; acc.y += p.y; acc.z += p.z; acc.w += p.w;
    }
    float4 o;
    o.x = 1.0f / acc.x; o.y = 1.0f / acc.y; o.z = 1.0f / acc.z; o.w = 1.0f / acc.w;
    ((float4*)g_c)[jv] = o;
}

__global__ void diag_kernel(void) {
    int j = blockIdx.x * blockDim.x + threadIdx.x;
    const __nv_bfloat16* K = (const __nv_bfloat16*)g_K4;
    g_d[j] = __bfloat162float(K[(size_t)j * N + j]) * g_r[j] * g_c[j];
}

// ============================================================================
// loss_fused: batched loads (RB rows), zero per-row syncs.
// ============================================================================
__global__ __launch_bounds__(THREADS, 1) void loss_fused(void) {
    int t = threadIdx.x;
    int wid = t >> 5, lane = t & 31;
    int row0 = blockIdx.x * ROWS_PER_BLOCK;
    __shared__ float rsm[ROWS_PER_BLOCK], dsm[ROWS_PER_BLOCK];
    __shared__ float red[16];

    if (t < ROWS_PER_BLOCK) {
        rsm[t] = g_r[row0 + t];
        dsm[t] = g_d[row0 + t];
    }

    const uint4* __restrict__ kbase = g_K4 + (size_t)row0 * NU4 + t * 2;
    float c[CPT], dj[CPT];
    {
        const float4* cp = (const float4*)g_c + t * 4;
        const float4* dp = (const float4*)g_d + t * 4;
        #pragma unroll
        for (int q = 0; q < 4; q++) {
            float4 v = cp[q];
            c[q * 4] = v.x; c[q * 4 + 1] = v.y; c[q * 4 + 2] = v.z; c[q * 4 + 3] = v.w;
            float4 w = dp[q];
            dj[q * 4] = w.x; dj[q * 4 + 1] = w.y; dj[q * 4 + 2] = w.z; dj[q * 4 + 3] = w.w;
        }
    }
    __syncthreads();

    int col0 = t * CPT;
    float l0 = 0.f, l1 = 0.f, l2 = 0.f, l3 = 0.f;

    for (int b = 0; b < ROWS_PER_BLOCK / RB; b++) {
        uint4 kp[RB][2];
        #pragma unroll
        for (int r = 0; r < RB; r++) {
            const uint4* p = kbase + (size_t)(b * RB + r) * NU4;
            kp[r][0] = p[0]; kp[r][1] = p[1];
        }
        #pragma unroll
        for (int r = 0; r < RB; r++) {
            float k[CPT];
            unpack16(kp[r][0], kp[r][1], k);
            int rr = b * RB + r;
            float ri = rsm[rr];
            float di = dsm[rr];
            int row = row0 + rr;
            #pragma unroll
            for (int i = 0; i < CPT; i++) {
                float P = k[i] * ri * c[i];
                float h = fmaxf(P - dj[i] + MARGIN, 0.f) + fmaxf(P - di + MARGIN, 0.f);
                h = (col0 + i != row) ? h : 0.f;
                if ((i & 3) == 0) l0 += h;
                else if ((i & 3) == 1) l1 += h;
                else if ((i & 3) == 2) l2 += h;
                else l3 += h;
            }
        }
    }

    float s = warp_sum((l0 + l1) + (l2 + l3));
    if (lane == 0) red[wid] = s;
    __syncthreads();
    if (wid == 0) {
        float v = (lane < 16) ? red[lane] : 0.f;
        v = warp_sum(v);
        if (lane == 0) g_block_loss[blockIdx.x] = v;
    }
}

__global__ void final_reduce_kernel(float* __restrict__ out) {
    __shared__ double sh[256];
    double acc = (threadIdx.x < BLOCKS) ? (double)g_block_loss[threadIdx.x] : 0.0;
    sh[threadIdx.x] = acc;
    __syncthreads();
    #pragma unroll
    for (int s = 128; s > 0; s >>= 1) {
        if (threadIdx.x < s) sh[threadIdx.x] += sh[threadIdx.x + s];
        __syncthreads();
    }
    if (threadIdx.x == 0) out[0] = (float)sh[0];
}

extern "C" void kernel_launch(void* const* d_in, const int* in_sizes, int n_in,
                              void* d_out, int out_size) {
    const float* sims = (const float*)d_in[0];
    float* out = (float*)d_out;

    pass1_fused<<<BLOCKS, THREADS>>>(sims);
    col_reduce1<<<dim3(8, RGROUPS), 256>>>();
    col_reduce2<<<8, 256>>>();

    for (int it = 1; it < 5; it++) {
        fused_pass<<<BLOCKS, THREADS>>>();
        col_reduce1<<<dim3(8, RGROUPS), 256>>>();
        col_reduce2<<<8, 256>>>();
    }

    diag_kernel<<<32, 256>>>();
    loss_fused<<<BLOCKS, THREADS>>>();
    final_reduce_kernel<<<1, 256>>>(out);
}

// round 7
// speedup vs baseline: 1.0775x; 1.0775x over previous
#include <cuda_runtime.h>
#include <cuda_bf16.h>

#define N 8192
#define MARGIN 0.2f
#define INV_LAMB 83.333336f   // 1 / 0.012

#define BLOCKS 512
#define RPB 16                // rows per block: 512 * 16 = 8192
#define THREADS 512
#define CPT 16                // columns per thread: 512 * 16 = 8192
#define NU4 1024              // uint4 (8 bf16) per row
#define NF4 2048              // float4 per row
#define PGROUPS 16            // 512 partial rows -> 16 groups of 32

// ---- scratch (static __device__ globals; no allocations) ----
__device__ uint4  g_K4[(size_t)N * N / 8];        // K in bf16 (128 MB)
__device__ float  g_r[N];
__device__ float  g_c[N];
__device__ float  g_d[N];
__device__ float  g_partial[(size_t)BLOCKS * N];  // col partials (16 MB)
__device__ float  g_partial2[(size_t)PGROUPS * N];// stage-2 partials (512 KB)
__device__ float  g_block_loss[BLOCKS];

__device__ __forceinline__ float warp_sum(float v) {
    v += __shfl_xor_sync(0xffffffffu, v, 16);
    v += __shfl_xor_sync(0xffffffffu, v, 8);
    v += __shfl_xor_sync(0xffffffffu, v, 4);
    v += __shfl_xor_sync(0xffffffffu, v, 2);
    v += __shfl_xor_sync(0xffffffffu, v, 1);
    return v;
}

__device__ __forceinline__ float2 unpack_bf2(unsigned u) {
    float2 f;
    f.x = __uint_as_float(u << 16);
    f.y = __uint_as_float(u & 0xffff0000u);
    return f;
}

__device__ __forceinline__ unsigned pack_bf2(float lo, float hi) {
    __nv_bfloat162 h = __floats2bfloat162_rn(lo, hi);
    return *reinterpret_cast<unsigned*>(&h);
}

__device__ __forceinline__ void unpack16(const uint4& a, const uint4& b, float* k) {
    float2 p;
    p = unpack_bf2(a.x); k[0] = p.x;  k[1] = p.y;
    p = unpack_bf2(a.y); k[2] = p.x;  k[3] = p.y;
    p = unpack_bf2(a.z); k[4] = p.x;  k[5] = p.y;
    p = unpack_bf2(a.w); k[6] = p.x;  k[7] = p.y;
    p = unpack_bf2(b.x); k[8] = p.x;  k[9] = p.y;
    p = unpack_bf2(b.y); k[10] = p.x; k[11] = p.y;
    p = unpack_bf2(b.z); k[12] = p.x; k[13] = p.y;
    p = unpack_bf2(b.w); k[14] = p.x; k[15] = p.y;
}

// ============================================================================
// pass1_fused: K = exp((s-1)/lamb) -> bf16 cache; row update with c == 1;
// col partials with new r.  512 CTAs x 16 rows; lean registers, occ 2.
// ============================================================================
__global__ __launch_bounds__(THREADS, 2) void pass1_fused(const float* __restrict__ sims) {
    int t = threadIdx.x;
    int wid = t >> 5, lane = t & 31;
    int row0 = blockIdx.x * RPB;
    __shared__ float red[2][16];

    const float4* __restrict__ sbase = (const float4*)sims + (size_t)row0 * NF4 + t * 4;
    uint4* __restrict__ kbase = g_K4 + (size_t)row0 * NU4 + t * 2;

    float acc[CPT];
    #pragma unroll
    for (int i = 0; i < CPT; i++) acc[i] = 0.f;

    for (int r = 0; r < RPB; r++) {
        const float4* sp = sbase + (size_t)r * NF4;
        float4 s0 = sp[0], s1 = sp[1], s2 = sp[2], s3 = sp[3];
        float k[CPT];
        k[0]  = __expf((s0.x - 1.0f) * INV_LAMB);
        k[1]  = __expf((s0.y - 1.0f) * INV_LAMB);
        k[2]  = __expf((s0.z - 1.0f) * INV_LAMB);
        k[3]  = __expf((s0.w - 1.0f) * INV_LAMB);
        k[4]  = __expf((s1.x - 1.0f) * INV_LAMB);
        k[5]  = __expf((s1.y - 1.0f) * INV_LAMB);
        k[6]  = __expf((s1.z - 1.0f) * INV_LAMB);
        k[7]  = __expf((s1.w - 1.0f) * INV_LAMB);
        k[8]  = __expf((s2.x - 1.0f) * INV_LAMB);
        k[9]  = __expf((s2.y - 1.0f) * INV_LAMB);
        k[10] = __expf((s2.z - 1.0f) * INV_LAMB);
        k[11] = __expf((s2.w - 1.0f) * INV_LAMB);
        k[12] = __expf((s3.x - 1.0f) * INV_LAMB);
        k[13] = __expf((s3.y - 1.0f) * INV_LAMB);
        k[14] = __expf((s3.z - 1.0f) * INV_LAMB);
        k[15] = __expf((s3.w - 1.0f) * INV_LAMB);

        uint4 o0, o1;
        o0.x = pack_bf2(k[0], k[1]);   o0.y = pack_bf2(k[2], k[3]);
        o0.z = pack_bf2(k[4], k[5]);   o0.w = pack_bf2(k[6], k[7]);
        o1.x = pack_bf2(k[8], k[9]);   o1.y = pack_bf2(k[10], k[11]);
        o1.z = pack_bf2(k[12], k[13]); o1.w = pack_bf2(k[14], k[15]);
        uint4* op = kbase + (size_t)r * NU4;
        op[0] = o0; op[1] = o1;

        float a = 0.f, b = 0.f, c2 = 0.f, d2 = 0.f;
        #pragma unroll
        for (int i = 0; i < CPT; i += 4) {
            a += k[i]; b += k[i + 1]; c2 += k[i + 2]; d2 += k[i + 3];
        }
        float s = warp_sum((a + b) + (c2 + d2));
        if (lane == 0) red[r & 1][wid] = s;
        __syncthreads();
        float tot = 0.f;
        #pragma unroll
        for (int w = 0; w < 16; w++) tot += red[r & 1][w];
        float ri = 1.0f / tot;
        if (t == r) g_r[row0 + r] = ri;
        #pragma unroll
        for (int i = 0; i < CPT; i++) acc[i] += k[i] * ri;
    }

    float4* out = (float4*)(g_partial + (size_t)blockIdx.x * N) + t * 4;
    #pragma unroll
    for (int q = 0; q < 4; q++)
        out[q] = make_float4(acc[q * 4], acc[q * 4 + 1], acc[q * 4 + 2], acc[q * 4 + 3]);
}

// ============================================================================
// fused_pass: r_i = 1/sum_j K_ij c_j, col partials sum_i K_ij r_i, ONE read
// of K.  c lives in smem (float4-interleaved, conflict-free); depth-1
// prefetch; 512 CTAs x 16 rows; occ 2.
// ============================================================================
__global__ __launch_bounds__(THREADS, 2) void fused_pass(void) {
    int t = threadIdx.x;
    int wid = t >> 5, lane = t & 31;
    int row0 = blockIdx.x * RPB;
    __shared__ float4 c_sm[4 * THREADS];   // c_sm[q*512 + t] = g_c4[4t + q]
    __shared__ float red[2][16];

    {
        const float4* cg = (const float4*)g_c;
        #pragma unroll
        for (int q = 0; q < 4; q++) c_sm[q * THREADS + t] = cg[t * 4 + q];
    }
    __syncthreads();

    const uint4* __restrict__ kbase = g_K4 + (size_t)row0 * NU4 + t * 2;

    float acc[CPT];
    #pragma unroll
    for (int i = 0; i < CPT; i++) acc[i] = 0.f;

    uint4 cur0 = kbase[0], cur1 = kbase[1];

    for (int r = 0; r < RPB; r++) {
        uint4 nx0, nx1;
        if (r + 1 < RPB) {
            const uint4* p = kbase + (size_t)(r + 1) * NU4;
            nx0 = p[0]; nx1 = p[1];
        }
        float k[CPT];
        unpack16(cur0, cur1, k);

        float4 c0 = c_sm[t];
        float4 c1 = c_sm[THREADS + t];
        float4 c2 = c_sm[2 * THREADS + t];
        float4 c3 = c_sm[3 * THREADS + t];

        float a = k[0] * c0.x + k[4] * c1.x + k[8] * c2.x + k[12] * c3.x;
        float b = k[1] * c0.y + k[5] * c1.y + k[9] * c2.y + k[13] * c3.y;
        float cc = k[2] * c0.z + k[6] * c1.z + k[10] * c2.z + k[14] * c3.z;
        float d = k[3] * c0.w + k[7] * c1.w + k[11] * c2.w + k[15] * c3.w;

        float s = warp_sum((a + b) + (cc + d));
        if (lane == 0) red[r & 1][wid] = s;
        __syncthreads();
        float tot = 0.f;
        #pragma unroll
        for (int w = 0; w < 16; w++) tot += red[r & 1][w];
        float ri = 1.0f / tot;
        if (t == r) g_r[row0 + r] = ri;
        #pragma unroll
        for (int i = 0; i < CPT; i++) acc[i] += k[i] * ri;

        cur0 = nx0; cur1 = nx1;
    }

    float4* out = (float4*)(g_partial + (size_t)blockIdx.x * N) + t * 4;
    #pragma unroll
    for (int q = 0; q < 4; q++)
        out[q] = make_float4(acc[q * 4], acc[q * 4 + 1], acc[q * 4 + 2], acc[q * 4 + 3]);
}

// ============================================================================
// Two-stage tree reduction of g_partial[512][N] -> g_c
// ============================================================================
__global__ void col_reduce1(void) {
    int jv = blockIdx.x * 256 + threadIdx.x;   // float4 col index 0..2047
    int g  = blockIdx.y;
    const float4* __restrict__ p4 = (const float4*)g_partial;
    float4 acc = make_float4(0.f, 0.f, 0.f, 0.f);
    #pragma unroll
    for (int b = 0; b < 32; b++) {
        float4 p = p4[(size_t)(g * 32 + b) * (N / 4) + jv];
        acc.x += p.x; acc.y += p.y; acc.z += p.z; acc.w += p.w;
    }
    ((float4*)g_partial2)[(size_t)g * (N / 4) + jv] = acc;
}

__global__ void col_reduce2(void) {
    int jv = blockIdx.x * 256 + threadIdx.x;
    const float4* __restrict__ p4 = (const float4*)g_partial2;
    float4 acc = make_float4(0.f, 0.f, 0.f, 0.f);
    #pragma unroll
    for (int g = 0; g < PGROUPS; g++) {
        float4 p = p4[(size_t)g * (N / 4) + jv];
        acc.x += p.x; acc.y += p.y; acc.z += p.z; acc.w += p.w;
    }
    float4 o;
    o.x = 1.0f / acc.x; o.y = 1.0f / acc.y; o.z = 1.0f / acc.z; o.w = 1.0f / acc.w;
    ((float4*)g_c)[jv] = o;
}

__global__ void diag_kernel(void) {
    int j = blockIdx.x * blockDim.x + threadIdx.x;
    const __nv_bfloat16* K = (const __nv_bfloat16*)g_K4;
    g_d[j] = __bfloat162float(K[(size_t)j * N + j]) * g_r[j] * g_c[j];
}

// ============================================================================
// loss_fused: c in smem, dj in registers; depth-1 prefetch; no per-row syncs.
// ============================================================================
__global__ __launch_bounds__(THREADS, 2) void loss_fused(void) {
    int t = threadIdx.x;
    int wid = t >> 5, lane = t & 31;
    int row0 = blockIdx.x * RPB;
    __shared__ float4 c_sm[4 * THREADS];
    __shared__ float rsm[RPB], dsm[RPB];
    __shared__ float red[16];

    {
        const float4* cg = (const float4*)g_c;
        #pragma unroll
        for (int q = 0; q < 4; q++) c_sm[q * THREADS + t] = cg[t * 4 + q];
    }
    if (t < RPB) {
        rsm[t] = g_r[row0 + t];
        dsm[t] = g_d[row0 + t];
    }

    float dj[CPT];
    {
        const float4* dp = (const float4*)g_d + t * 4;
        #pragma unroll
        for (int q = 0; q < 4; q++) {
            float4 w = dp[q];
            dj[q * 4] = w.x; dj[q * 4 + 1] = w.y; dj[q * 4 + 2] = w.z; dj[q * 4 + 3] = w.w;
        }
    }
    __syncthreads();

    const uint4* __restrict__ kbase = g_K4 + (size_t)row0 * NU4 + t * 2;
    int col0 = t * CPT;
    float l0 = 0.f, l1 = 0.f, l2 = 0.f, l3 = 0.f;

    uint4 cur0 = kbase[0], cur1 = kbase[1];

    for (int r = 0; r < RPB; r++) {
        uint4 nx0, nx1;
        if (r + 1 < RPB) {
            const uint4* p = kbase + (size_t)(r + 1) * NU4;
            nx0 = p[0]; nx1 = p[1];
        }
        float k[CPT];
        unpack16(cur0, cur1, k);

        float4 c0 = c_sm[t];
        float4 c1 = c_sm[THREADS + t];
        float4 c2 = c_sm[2 * THREADS + t];
        float4 c3 = c_sm[3 * THREADS + t];
        float cv[CPT] = {c0.x, c0.y, c0.z, c0.w, c1.x, c1.y, c1.z, c1.w,
                         c2.x, c2.y, c2.z, c2.w, c3.x, c3.y, c3.z, c3.w};
        // cv index mapping must match k: k[i] covers column col0+i, whose c is
        // g_c[col0+i]. c_sm[q*512+t] = cols 16t+4q..+3 -> for k[i], q = i/4.
        // cv above is ordered [c(q0),c(q1),c(q2),c(q3)] = cols (16t+0..3),(4..7),... ✓

        float ri = rsm[r];
        float di = dsm[r];
        int row = row0 + r;
        #pragma unroll
        for (int i = 0; i < CPT; i++) {
            float P = k[i] * ri * cv[i];
            float h = fmaxf(P - dj[i] + MARGIN, 0.f) + fmaxf(P - di + MARGIN, 0.f);
            h = (col0 + i != row) ? h : 0.f;
            if ((i & 3) == 0) l0 += h;
            else if ((i & 3) == 1) l1 += h;
            else if ((i & 3) == 2) l2 += h;
            else l3 += h;
        }
        cur0 = nx0; cur1 = nx1;
    }

    float s = warp_sum((l0 + l1) + (l2 + l3));
    if (lane == 0) red[wid] = s;
    __syncthreads();
    if (wid == 0) {
        float v = (lane < 16) ? red[lane] : 0.f;
        v = warp_sum(v);
        if (lane == 0) g_block_loss[blockIdx.x] = v;
    }
}

__global__ void final_reduce_kernel(float* __restrict__ out) {
    __shared__ double sh[256];
    double acc = 0.0;
    for (int i = threadIdx.x; i < BLOCKS; i += 256) acc += (double)g_block_loss[i];
    sh[threadIdx.x] = acc;
    __syncthreads();
    #pragma unroll
    for (int s = 128; s > 0; s >>= 1) {
        if (threadIdx.x < s) sh[threadIdx.x] += sh[threadIdx.x + s];
        __syncthreads();
    }
    if (threadIdx.x == 0) out[0] = (float)sh[0];
}

extern "C" void kernel_launch(void* const* d_in, const int* in_sizes, int n_in,
                              void* d_out, int out_size) {
    const float* sims = (const float*)d_in[0];
    float* out = (float*)d_out;

    pass1_fused<<<BLOCKS, THREADS>>>(sims);
    col_reduce1<<<dim3(8, PGROUPS), 256>>>();
    col_reduce2<<<16, 256>>>();

    for (int it = 1; it < 5; it++) {
        fused_pass<<<BLOCKS, THREADS>>>();
        col_reduce1<<<dim3(8, PGROUPS), 256>>>();
        col_reduce2<<<16, 256>>>();
    }

    diag_kernel<<<32, 256>>>();
    loss_fused<<<BLOCKS, THREADS>>>();
    final_reduce_kernel<<<1, 256>>>(out);
}

// round 8
// speedup vs baseline: 1.1073x; 1.0276x over previous
#include <cuda_runtime.h>
#include <cuda_bf16.h>

#define N 8192
#define MARGIN 0.2f
#define INV_LAMB 83.333336f   // 1 / 0.012

#define BLOCKS 512
#define RPB 16                // rows per block: 512 * 16 = 8192
#define THREADS 512
#define CPT 16                // columns per thread: 512 * 16 = 8192
#define NU4 1024              // uint4 (8 bf16) per row
#define NF4 2048              // float4 per row
#define PGROUPS 16            // 512 partial rows -> 16 groups of 32

// ---- scratch (static __device__ globals; no allocations) ----
__device__ uint4  g_K4[(size_t)N * N / 8];        // K in bf16 (128 MB)
__device__ float  g_r[N];
__device__ float  g_c[N];
__device__ float  g_d[N];
__device__ float  g_partial[(size_t)BLOCKS * N];  // col partials (16 MB)
__device__ float  g_partial2[(size_t)PGROUPS * N];// stage-2 partials (512 KB)
__device__ float  g_block_loss[BLOCKS];

__device__ __forceinline__ float warp_sum(float v) {
    v += __shfl_xor_sync(0xffffffffu, v, 16);
    v += __shfl_xor_sync(0xffffffffu, v, 8);
    v += __shfl_xor_sync(0xffffffffu, v, 4);
    v += __shfl_xor_sync(0xffffffffu, v, 2);
    v += __shfl_xor_sync(0xffffffffu, v, 1);
    return v;
}

__device__ __forceinline__ float2 unpack_bf2(unsigned u) {
    float2 f;
    f.x = __uint_as_float(u << 16);
    f.y = __uint_as_float(u & 0xffff0000u);
    return f;
}

__device__ __forceinline__ unsigned pack_bf2(float lo, float hi) {
    __nv_bfloat162 h = __floats2bfloat162_rn(lo, hi);
    return *reinterpret_cast<unsigned*>(&h);
}

// ============================================================================
// pass1_fused: K = exp((s-1)/lamb) -> bf16 cache; row update with c == 1;
// col partials with new r.  512 CTAs x 16 rows.
// ============================================================================
__global__ __launch_bounds__(THREADS, 2) void pass1_fused(const float* __restrict__ sims) {
    int t = threadIdx.x;
    int wid = t >> 5, lane = t & 31;
    int row0 = blockIdx.x * RPB;
    __shared__ float red[2][16];

    const float4* __restrict__ sbase = (const float4*)sims + (size_t)row0 * NF4 + t * 4;
    uint4* __restrict__ kbase = g_K4 + (size_t)row0 * NU4 + t * 2;

    float acc[CPT];
    #pragma unroll
    for (int i = 0; i < CPT; i++) acc[i] = 0.f;

    for (int r = 0; r < RPB; r++) {
        const float4* sp = sbase + (size_t)r * NF4;
        float4 s0 = sp[0], s1 = sp[1], s2 = sp[2], s3 = sp[3];
        float k[CPT];
        k[0]  = __expf((s0.x - 1.0f) * INV_LAMB);
        k[1]  = __expf((s0.y - 1.0f) * INV_LAMB);
        k[2]  = __expf((s0.z - 1.0f) * INV_LAMB);
        k[3]  = __expf((s0.w - 1.0f) * INV_LAMB);
        k[4]  = __expf((s1.x - 1.0f) * INV_LAMB);
        k[5]  = __expf((s1.y - 1.0f) * INV_LAMB);
        k[6]  = __expf((s1.z - 1.0f) * INV_LAMB);
        k[7]  = __expf((s1.w - 1.0f) * INV_LAMB);
        k[8]  = __expf((s2.x - 1.0f) * INV_LAMB);
        k[9]  = __expf((s2.y - 1.0f) * INV_LAMB);
        k[10] = __expf((s2.z - 1.0f) * INV_LAMB);
        k[11] = __expf((s2.w - 1.0f) * INV_LAMB);
        k[12] = __expf((s3.x - 1.0f) * INV_LAMB);
        k[13] = __expf((s3.y - 1.0f) * INV_LAMB);
        k[14] = __expf((s3.z - 1.0f) * INV_LAMB);
        k[15] = __expf((s3.w - 1.0f) * INV_LAMB);

        uint4 o0, o1;
        o0.x = pack_bf2(k[0], k[1]);   o0.y = pack_bf2(k[2], k[3]);
        o0.z = pack_bf2(k[4], k[5]);   o0.w = pack_bf2(k[6], k[7]);
        o1.x = pack_bf2(k[8], k[9]);   o1.y = pack_bf2(k[10], k[11]);
        o1.z = pack_bf2(k[12], k[13]); o1.w = pack_bf2(k[14], k[15]);
        uint4* op = kbase + (size_t)r * NU4;
        op[0] = o0; op[1] = o1;

        float a = 0.f, b = 0.f, c2 = 0.f, d2 = 0.f;
        #pragma unroll
        for (int i = 0; i < CPT; i += 4) {
            a += k[i]; b += k[i + 1]; c2 += k[i + 2]; d2 += k[i + 3];
        }
        float s = warp_sum((a + b) + (c2 + d2));
        if (lane == 0) red[r & 1][wid] = s;
        __syncthreads();
        float tot = 0.f;
        #pragma unroll
        for (int w = 0; w < 16; w++) tot += red[r & 1][w];
        float ri = 1.0f / tot;
        if (t == r) g_r[row0 + r] = ri;
        #pragma unroll
        for (int i = 0; i < CPT; i++) acc[i] += k[i] * ri;
    }

    float4* out = (float4*)(g_partial + (size_t)blockIdx.x * N) + t * 4;
    #pragma unroll
    for (int q = 0; q < 4; q++)
        out[q] = make_float4(acc[q * 4], acc[q * 4 + 1], acc[q * 4 + 2], acc[q * 4 + 3]);
}

// ============================================================================
// fused_pass: r_i = 1/sum_j K_ij c_j, col partials sum_i K_ij r_i, ONE read
// of K.  c lives in REGISTERS; packed depth-1 prefetch; bf16 unpacked on the
// fly twice per row (saves 16 live regs across the barrier) -> <=64 regs,
// occ 2, no LDS traffic in the hot loop.
// ============================================================================
__global__ __launch_bounds__(THREADS, 2) void fused_pass(void) {
    int t = threadIdx.x;
    int wid = t >> 5, lane = t & 31;
    int row0 = blockIdx.x * RPB;
    __shared__ float red[2][16];

    const uint4* __restrict__ kbase = g_K4 + (size_t)row0 * NU4 + t * 2;

    float c[CPT];
    {
        const float4* cp = (const float4*)g_c + t * 4;
        #pragma unroll
        for (int q = 0; q < 4; q++) {
            float4 v = cp[q];
            c[q * 4] = v.x; c[q * 4 + 1] = v.y; c[q * 4 + 2] = v.z; c[q * 4 + 3] = v.w;
        }
    }
    float acc[CPT];
    #pragma unroll
    for (int i = 0; i < CPT; i++) acc[i] = 0.f;

    uint4 cur0 = kbase[0], cur1 = kbase[1];

    for (int r = 0; r < RPB; r++) {
        uint4 nx0, nx1;
        if (r + 1 < RPB) {
            const uint4* p = kbase + (size_t)(r + 1) * NU4;
            nx0 = p[0]; nx1 = p[1];
        }
        // ---- dot(K_row, c): unpack on the fly ----
        float a0 = 0.f, a1 = 0.f, a2 = 0.f, a3 = 0.f;
        {
            float2 p;
            p = unpack_bf2(cur0.x); a0 += p.x * c[0];  a1 += p.y * c[1];
            p = unpack_bf2(cur0.y); a2 += p.x * c[2];  a3 += p.y * c[3];
            p = unpack_bf2(cur0.z); a0 += p.x * c[4];  a1 += p.y * c[5];
            p = unpack_bf2(cur0.w); a2 += p.x * c[6];  a3 += p.y * c[7];
            p = unpack_bf2(cur1.x); a0 += p.x * c[8];  a1 += p.y * c[9];
            p = unpack_bf2(cur1.y); a2 += p.x * c[10]; a3 += p.y * c[11];
            p = unpack_bf2(cur1.z); a0 += p.x * c[12]; a1 += p.y * c[13];
            p = unpack_bf2(cur1.w); a2 += p.x * c[14]; a3 += p.y * c[15];
        }
        float s = warp_sum((a0 + a1) + (a2 + a3));
        if (lane == 0) red[r & 1][wid] = s;
        __syncthreads();
        float tot = 0.f;
        #pragma unroll
        for (int w = 0; w < 16; w++) tot += red[r & 1][w];
        float ri = 1.0f / tot;
        if (t == r) g_r[row0 + r] = ri;
        // ---- accumulate col partials: unpack again ----
        {
            float2 p;
            p = unpack_bf2(cur0.x); acc[0]  += p.x * ri; acc[1]  += p.y * ri;
            p = unpack_bf2(cur0.y); acc[2]  += p.x * ri; acc[3]  += p.y * ri;
            p = unpack_bf2(cur0.z); acc[4]  += p.x * ri; acc[5]  += p.y * ri;
            p = unpack_bf2(cur0.w); acc[6]  += p.x * ri; acc[7]  += p.y * ri;
            p = unpack_bf2(cur1.x); acc[8]  += p.x * ri; acc[9]  += p.y * ri;
            p = unpack_bf2(cur1.y); acc[10] += p.x * ri; acc[11] += p.y * ri;
            p = unpack_bf2(cur1.z); acc[12] += p.x * ri; acc[13] += p.y * ri;
            p = unpack_bf2(cur1.w); acc[14] += p.x * ri; acc[15] += p.y * ri;
        }
        cur0 = nx0; cur1 = nx1;
    }

    float4* out = (float4*)(g_partial + (size_t)blockIdx.x * N) + t * 4;
    #pragma unroll
    for (int q = 0; q < 4; q++)
        out[q] = make_float4(acc[q * 4], acc[q * 4 + 1], acc[q * 4 + 2], acc[q * 4 + 3]);
}

// ============================================================================
// Two-stage tree reduction of g_partial[512][N] -> g_c
// ============================================================================
__global__ void col_reduce1(void) {
    int jv = blockIdx.x * 256 + threadIdx.x;   // float4 col index 0..2047
    int g  = blockIdx.y;
    const float4* __restrict__ p4 = (const float4*)g_partial;
    float4 acc = make_float4(0.f, 0.f, 0.f, 0.f);
    #pragma unroll
    for (int b = 0; b < 32; b++) {
        float4 p = p4[(size_t)(g * 32 + b) * (N / 4) + jv];
        acc.x += p.x; acc.y += p.y; acc.z += p.z; acc.w += p.w;
    }
    ((float4*)g_partial2)[(size_t)g * (N / 4) + jv] = acc;
}

__global__ void col_reduce2(void) {
    int jv = blockIdx.x * 256 + threadIdx.x;
    const float4* __restrict__ p4 = (const float4*)g_partial2;
    float4 acc = make_float4(0.f, 0.f, 0.f, 0.f);
    #pragma unroll
    for (int g = 0; g < PGROUPS; g++) {
        float4 p = p4[(size_t)g * (N / 4) + jv];
        acc.x += p.x; acc.y += p.y; acc.z += p.z; acc.w += p.w;
    }
    float4 o;
    o.x = 1.0f / acc.x; o.y = 1.0f / acc.y; o.z = 1.0f / acc.z; o.w = 1.0f / acc.w;
    ((float4*)g_c)[jv] = o;
}

__global__ void diag_kernel(void) {
    int j = blockIdx.x * blockDim.x + threadIdx.x;
    const __nv_bfloat16* K = (const __nv_bfloat16*)g_K4;
    g_d[j] = __bfloat162float(K[(size_t)j * N + j]) * g_r[j] * g_c[j];
}

// ============================================================================
// loss_fused: c and dj in registers; packed depth-1 prefetch; inline unpack;
// no per-row syncs.
// ============================================================================
__global__ __launch_bounds__(THREADS, 2) void loss_fused(void) {
    int t = threadIdx.x;
    int wid = t >> 5, lane = t & 31;
    int row0 = blockIdx.x * RPB;
    __shared__ float rsm[RPB], dsm[RPB];
    __shared__ float red[16];

    if (t < RPB) {
        rsm[t] = g_r[row0 + t];
        dsm[t] = g_d[row0 + t];
    }

    float c[CPT], dj[CPT];
    {
        const float4* cp = (const float4*)g_c + t * 4;
        const float4* dp = (const float4*)g_d + t * 4;
        #pragma unroll
        for (int q = 0; q < 4; q++) {
            float4 v = cp[q];
            c[q * 4] = v.x; c[q * 4 + 1] = v.y; c[q * 4 + 2] = v.z; c[q * 4 + 3] = v.w;
            float4 w = dp[q];
            dj[q * 4] = w.x; dj[q * 4 + 1] = w.y; dj[q * 4 + 2] = w.z; dj[q * 4 + 3] = w.w;
        }
    }
    __syncthreads();

    const uint4* __restrict__ kbase = g_K4 + (size_t)row0 * NU4 + t * 2;
    int col0 = t * CPT;
    float l0 = 0.f, l1 = 0.f, l2 = 0.f, l3 = 0.f;

    uint4 cur0 = kbase[0], cur1 = kbase[1];

    for (int r = 0; r < RPB; r++) {
        uint4 nx0, nx1;
        if (r + 1 < RPB) {
            const uint4* p = kbase + (size_t)(r + 1) * NU4;
            nx0 = p[0]; nx1 = p[1];
        }
        float ri = rsm[r];
        float di = dsm[r];
        int row = row0 + r;

        unsigned pk[8] = {cur0.x, cur0.y, cur0.z, cur0.w, cur1.x, cur1.y, cur1.z, cur1.w};
        #pragma unroll
        for (int q = 0; q < 8; q++) {
            float2 p = unpack_bf2(pk[q]);
            int i0 = q * 2;
            float P = p.x * ri * c[i0];
            float h = fmaxf(P - dj[i0] + MARGIN, 0.f) + fmaxf(P - di + MARGIN, 0.f);
            if (col0 + i0 != row) { if (q & 1) l1 += h; else l0 += h; }
            P = p.y * ri * c[i0 + 1];
            h = fmaxf(P - dj[i0 + 1] + MARGIN, 0.f) + fmaxf(P - di + MARGIN, 0.f);
            if (col0 + i0 + 1 != row) { if (q & 1) l3 += h; else l2 += h; }
        }
        cur0 = nx0; cur1 = nx1;
    }

    float s = warp_sum((l0 + l1) + (l2 + l3));
    if (lane == 0) red[wid] = s;
    __syncthreads();
    if (wid == 0) {
        float v = (lane < 16) ? red[lane] : 0.f;
        v = warp_sum(v);
        if (lane == 0) g_block_loss[blockIdx.x] = v;
    }
}

__global__ void final_reduce_kernel(float* __restrict__ out) {
    __shared__ double sh[256];
    double acc = 0.0;
    for (int i = threadIdx.x; i < BLOCKS; i += 256) acc += (double)g_block_loss[i];
    sh[threadIdx.x] = acc;
    __syncthreads();
    #pragma unroll
    for (int s = 128; s > 0; s >>= 1) {
        if (threadIdx.x < s) sh[threadIdx.x] += sh[threadIdx.x + s];
        __syncthreads();
    }
    if (threadIdx.x == 0) out[0] = (float)sh[0];
}

extern "C" void kernel_launch(void* const* d_in, const int* in_sizes, int n_in,
                              void* d_out, int out_size) {
    const float* sims = (const float*)d_in[0];
    float* out = (float*)d_out;

    pass1_fused<<<BLOCKS, THREADS>>>(sims);
    col_reduce1<<<dim3(8, PGROUPS), 256>>>();
    col_reduce2<<<16, 256>>>();

    for (int it = 1; it < 5; it++) {
        fused_pass<<<BLOCKS, THREADS>>>();
        col_reduce1<<<dim3(8, PGROUPS), 256>>>();
        col_reduce2<<<16, 256>>>();
    }

    diag_kernel<<<32, 256>>>();
    loss_fused<<<BLOCKS, THREADS>>>();
    final_reduce_kernel<<<1, 256>>>(out);
}